// round 1
// baseline (speedup 1.0000x reference)
#include <cuda_runtime.h>
#include <cstdint>
#include <math.h>

// Problem constants
#define BB 8
#define TT 256
#define NN 512
#define CC 64
#define BT 2048           // BB*TT
#define BTN 1048576       // BB*TT*NN
#define HN 67108864       // BTN*CC elements per feature map
#define ALPHA 0.05f

// ---------------- device scratch (allocation-free rule: __device__ globals) ---
__device__ float g_h  [HN];
__device__ float g_h1f[HN];
__device__ float g_h2f[HN];
__device__ float g_h1r[HN];
__device__ float g_h2r[HN];
__device__ float g_Af [NN * NN];
__device__ float g_Ar [NN * NN];
__device__ float g_Wpad[7 * 64 * 128];   // [d][cin][c]  c<64 filter, c>=64 gate
__device__ float g_bconv[128];
__device__ float g_Wfin[320 * 128];      // [k][c]  c<64 -> out, c>=64 -> skip
__device__ float g_bfin[128];

struct P {
    const float* x; const float* adj;
    const float* wf[4]; const float* bf[4];
    const float* wg[4]; const float* bg[4];
    const float* Wgf; const float* bgf;
    const float* Wgr; const float* bgr;
    const float* Ws;  const float* bs;
};

// ---------------- prep: row-normalized adjacencies --------------------------
__global__ void prep_adj(const float* __restrict__ adj) {
    int n = blockIdx.x, tid = threadIdx.x;
    __shared__ float red[256];
    float s1 = 0.f, s2 = 0.f;
    for (int m = tid; m < NN; m += 256) {
        s1 += adj[n * NN + m];
        s2 += adj[m * NN + n];
    }
    red[tid] = s1; __syncthreads();
    for (int k = 128; k; k >>= 1) { if (tid < k) red[tid] += red[tid + k]; __syncthreads(); }
    float inv1 = 1.f / fmaxf(red[0] + 1.f, 1e-9f);
    __syncthreads();
    red[tid] = s2; __syncthreads();
    for (int k = 128; k; k >>= 1) { if (tid < k) red[tid] += red[tid + k]; __syncthreads(); }
    float inv2 = 1.f / fmaxf(red[0] + 1.f, 1e-9f);
    for (int m = tid; m < NN; m += 256) {
        g_Af[n * NN + m] = (adj[n * NN + m] + (m == n ? 1.f : 0.f)) * inv1;
        g_Ar[n * NN + m] = (adj[m * NN + n] + (m == n ? 1.f : 0.f)) * inv2;
    }
}

// ---------------- prep: packed weights ---------------------------------------
__global__ void prep_w(P p) {
    int idx = blockIdx.x * blockDim.x + threadIdx.x;
    const int KR[4] = {2, 3, 6, 7};
    if (idx < 57344) {
        // Wpad[d][cin][c]
        int d   = idx / (64 * 128);
        int rem = idx % (64 * 128);
        int cin = rem / 128;
        int c   = rem % 128;
        int cl = c & 63, i = cl >> 4, r = cl & 15;
        int k = KR[i], j = k - 1 - d;
        float v = 0.f;
        if (j >= 0) {
            const float* w = (c < 64) ? p.wf[i] : p.wg[i];
            v = w[(j * 64 + cin) * 16 + r];
        }
        g_Wpad[idx] = v;
        return;
    }
    int idx2 = idx - 57344;
    if (idx2 < 128) {
        int c = idx2, cl = c & 63, i = cl >> 4, r = cl & 15;
        g_bconv[c] = (c < 64) ? p.bf[i][r] : p.bg[i][r];
        return;
    }
    int idx3 = idx - 57472;
    if (idx3 < 40960) {
        int k = idx3 / 128, c = idx3 % 128;
        float v = 0.f;
        if (c < 64) {
            int s = k >> 6, kk = k & 63;
            if      (s == 0) v = p.Wgf[kk * 64 + c] + p.Wgr[kk * 64 + c];
            else if (s == 1) v = p.Wgf[( 64 + kk) * 64 + c];
            else if (s == 2) v = p.Wgf[(128 + kk) * 64 + c];
            else if (s == 3) v = p.Wgr[( 64 + kk) * 64 + c];
            else             v = p.Wgr[(128 + kk) * 64 + c];
        } else {
            if (k < 64) v = p.Ws[k * 64 + (c - 64)];
        }
        g_Wfin[idx3] = v;
        return;
    }
    int idx4 = idx - 98432;
    if (idx4 >= 0 && idx4 < 128) {
        g_bfin[idx4] = (idx4 < 64) ? (p.bgf[idx4] + p.bgr[idx4]) : p.bs[idx4 - 64];
    }
}

// ---------------- gated inception conv as shift-GEMM -------------------------
// CTA: 128 n-rows x 128 cols (64 filter + 64 gate), K = 7 shifts x 64 cin
__global__ __launch_bounds__(256) void conv_kernel(const float* __restrict__ x) {
    const int bt = blockIdx.y;            // b*TT + t
    const int t  = bt & (TT - 1);
    const int n0 = blockIdx.x * 128;
    const int tid = threadIdx.x;
    const int tm = tid >> 4;              // 0..15 -> rows tm*8..+7
    const int tn = tid & 15;              // 0..15 -> cols tn*4..+3 and 64+tn*4..+3

    __shared__ float As[32][128];         // [k][n]
    __shared__ float Bs[32][128];         // [k][c]

    float acc[8][8];
#pragma unroll
    for (int u = 0; u < 8; ++u)
#pragma unroll
        for (int v = 0; v < 8; ++v) acc[u][v] = 0.f;

    for (int d = 0; d < 7; ++d) {
        if (t - d < 0) break;             // earlier taps are zero-padded
        const float* xp = x + ((size_t)(bt - d) * NN + n0) * CC;
        for (int half = 0; half < 2; ++half) {
            const int c0 = half * 32;
            __syncthreads();
            // A tile: 128 rows x 32 cin, transposed into [k][n]
#pragma unroll
            for (int it = 0; it < 4; ++it) {
                int li = tid + it * 256;         // 0..1023
                int row = li >> 3, c4 = li & 7;
                float4 v = *reinterpret_cast<const float4*>(xp + row * CC + c0 + c4 * 4);
                As[c4 * 4 + 0][row] = v.x;
                As[c4 * 4 + 1][row] = v.y;
                As[c4 * 4 + 2][row] = v.z;
                As[c4 * 4 + 3][row] = v.w;
            }
            // B tile: Wpad slice
            const float* wp = g_Wpad + (d * 64 + c0) * 128;
#pragma unroll
            for (int it = 0; it < 4; ++it) {
                int li = tid + it * 256;
                int kk = li >> 5, cq = li & 31;
                *reinterpret_cast<float4*>(&Bs[kk][cq * 4]) =
                    *reinterpret_cast<const float4*>(wp + kk * 128 + cq * 4);
            }
            __syncthreads();
#pragma unroll
            for (int kk = 0; kk < 32; ++kk) {
                float a[8], bb[8];
                *reinterpret_cast<float4*>(&a[0]) = *reinterpret_cast<float4*>(&As[kk][tm * 8]);
                *reinterpret_cast<float4*>(&a[4]) = *reinterpret_cast<float4*>(&As[kk][tm * 8 + 4]);
                *reinterpret_cast<float4*>(&bb[0]) = *reinterpret_cast<float4*>(&Bs[kk][tn * 4]);
                *reinterpret_cast<float4*>(&bb[4]) = *reinterpret_cast<float4*>(&Bs[kk][64 + tn * 4]);
#pragma unroll
                for (int u = 0; u < 8; ++u)
#pragma unroll
                    for (int v = 0; v < 8; ++v) acc[u][v] += a[u] * bb[v];
            }
        }
    }
    // epilogue: gated activation h = tanh(f+bf) * sigmoid(g+bg)
    float bf4[4], bg4[4];
#pragma unroll
    for (int v = 0; v < 4; ++v) {
        bf4[v] = g_bconv[tn * 4 + v];
        bg4[v] = g_bconv[64 + tn * 4 + v];
    }
#pragma unroll
    for (int u = 0; u < 8; ++u) {
        int row = tm * 8 + u;
        size_t base = ((size_t)bt * NN + n0 + row) * CC;
        float4 o;
        float* op = &o.x;
#pragma unroll
        for (int v = 0; v < 4; ++v) {
            float f = acc[u][v] + bf4[v];
            float g = acc[u][v + 4] + bg4[v];
            op[v] = tanhf(f) * (1.f / (1.f + expf(-g)));
        }
        *reinterpret_cast<float4*>(&g_h[base + tn * 4]) = o;
    }
}

// ---------------- mixprop hop: hout = alpha*h0 + (1-alpha) * A @ hin ----------
// CTA: 256 n-rows x 64 f-cols, K = 512
__global__ __launch_bounds__(256) void hop_kernel(int dir, int hop) {
    const float* A   = dir ? g_Ar : g_Af;
    const float* hin = (hop == 0) ? g_h : (dir ? g_h1r : g_h1f);
    float* hout      = (hop == 0) ? (dir ? g_h1r : g_h1f) : (dir ? g_h2r : g_h2f);

    const int bt = blockIdx.y;
    const int n0 = blockIdx.x * 256;
    const int tid = threadIdx.x;
    const int tm = tid >> 3;              // 0..31 -> rows tm*8..+7
    const int tn = tid & 7;               // 0..7  -> cols tn*4..+3 and 32+tn*4..+3

    __shared__ float As[32][256];
    __shared__ float Bs[32][64];

    float acc[8][8];
#pragma unroll
    for (int u = 0; u < 8; ++u)
#pragma unroll
        for (int v = 0; v < 8; ++v) acc[u][v] = 0.f;

    const float* hb = hin + (size_t)bt * NN * CC;

    for (int kc = 0; kc < 16; ++kc) {
        __syncthreads();
        // A tile: 256 rows x 32 cols, transposed
#pragma unroll
        for (int it = 0; it < 8; ++it) {
            int li = tid + it * 256;      // 0..2047
            int row = li >> 3, c4 = li & 7;
            float4 v = *reinterpret_cast<const float4*>(A + (size_t)(n0 + row) * NN + kc * 32 + c4 * 4);
            As[c4 * 4 + 0][row] = v.x;
            As[c4 * 4 + 1][row] = v.y;
            As[c4 * 4 + 2][row] = v.z;
            As[c4 * 4 + 3][row] = v.w;
        }
        // B tile: h slab rows kc*32..+31
#pragma unroll
        for (int it = 0; it < 2; ++it) {
            int li = tid + it * 256;      // 0..511
            int kk = li >> 4, f4 = li & 15;
            *reinterpret_cast<float4*>(&Bs[kk][f4 * 4]) =
                *reinterpret_cast<const float4*>(hb + (size_t)(kc * 32 + kk) * CC + f4 * 4);
        }
        __syncthreads();
#pragma unroll
        for (int kk = 0; kk < 32; ++kk) {
            float a[8], bb[8];
            *reinterpret_cast<float4*>(&a[0]) = *reinterpret_cast<float4*>(&As[kk][tm * 8]);
            *reinterpret_cast<float4*>(&a[4]) = *reinterpret_cast<float4*>(&As[kk][tm * 8 + 4]);
            *reinterpret_cast<float4*>(&bb[0]) = *reinterpret_cast<float4*>(&Bs[kk][tn * 4]);
            *reinterpret_cast<float4*>(&bb[4]) = *reinterpret_cast<float4*>(&Bs[kk][32 + tn * 4]);
#pragma unroll
            for (int u = 0; u < 8; ++u)
#pragma unroll
                for (int v = 0; v < 8; ++v) acc[u][v] += a[u] * bb[v];
        }
    }
#pragma unroll
    for (int u = 0; u < 8; ++u) {
        int row = tm * 8 + u;
        size_t base = ((size_t)bt * NN + n0 + row) * CC;
        float4 h0a = *reinterpret_cast<const float4*>(&g_h[base + tn * 4]);
        float4 h0b = *reinterpret_cast<const float4*>(&g_h[base + 32 + tn * 4]);
        float4 o1, o2;
        o1.x = ALPHA * h0a.x + (1.f - ALPHA) * acc[u][0];
        o1.y = ALPHA * h0a.y + (1.f - ALPHA) * acc[u][1];
        o1.z = ALPHA * h0a.z + (1.f - ALPHA) * acc[u][2];
        o1.w = ALPHA * h0a.w + (1.f - ALPHA) * acc[u][3];
        o2.x = ALPHA * h0b.x + (1.f - ALPHA) * acc[u][4];
        o2.y = ALPHA * h0b.y + (1.f - ALPHA) * acc[u][5];
        o2.z = ALPHA * h0b.z + (1.f - ALPHA) * acc[u][6];
        o2.w = ALPHA * h0b.w + (1.f - ALPHA) * acc[u][7];
        *reinterpret_cast<float4*>(&hout[base + tn * 4]) = o1;
        *reinterpret_cast<float4*>(&hout[base + 32 + tn * 4]) = o2;
    }
}

// ---------------- final: out = concat5 @ Wfin(:,:64)+bias+x ; skip = h@Ws+bs --
// CTA: 128 rows x 128 cols (64 out + 64 skip), K = 320
__global__ __launch_bounds__(256) void final_kernel(const float* __restrict__ x,
                                                    float* __restrict__ out) {
    const int r0 = blockIdx.x * 128;
    const int tid = threadIdx.x;
    const int tm = tid >> 4;              // 0..15
    const int tn = tid & 15;              // 0..15 -> cols tn*4 (out) and 64+tn*4 (skip)

    __shared__ float As[32][128];
    __shared__ float Bs[32][128];

    float acc[8][8];
#pragma unroll
    for (int u = 0; u < 8; ++u)
#pragma unroll
        for (int v = 0; v < 8; ++v) acc[u][v] = 0.f;

    for (int kc = 0; kc < 10; ++kc) {
        int kq = kc * 32;
        int s = kq >> 6, off = kq & 63;
        const float* src = (s == 0) ? g_h : (s == 1) ? g_h1f : (s == 2) ? g_h2f
                         : (s == 3) ? g_h1r : g_h2r;
        __syncthreads();
#pragma unroll
        for (int it = 0; it < 4; ++it) {
            int li = tid + it * 256;
            int row = li >> 3, c4 = li & 7;
            float4 v = *reinterpret_cast<const float4*>(src + (size_t)(r0 + row) * CC + off + c4 * 4);
            As[c4 * 4 + 0][row] = v.x;
            As[c4 * 4 + 1][row] = v.y;
            As[c4 * 4 + 2][row] = v.z;
            As[c4 * 4 + 3][row] = v.w;
        }
#pragma unroll
        for (int it = 0; it < 4; ++it) {
            int li = tid + it * 256;
            int kk = li >> 5, cq = li & 31;
            *reinterpret_cast<float4*>(&Bs[kk][cq * 4]) =
                *reinterpret_cast<const float4*>(g_Wfin + (size_t)(kq + kk) * 128 + cq * 4);
        }
        __syncthreads();
#pragma unroll
        for (int kk = 0; kk < 32; ++kk) {
            float a[8], bb[8];
            *reinterpret_cast<float4*>(&a[0]) = *reinterpret_cast<float4*>(&As[kk][tm * 8]);
            *reinterpret_cast<float4*>(&a[4]) = *reinterpret_cast<float4*>(&As[kk][tm * 8 + 4]);
            *reinterpret_cast<float4*>(&bb[0]) = *reinterpret_cast<float4*>(&Bs[kk][tn * 4]);
            *reinterpret_cast<float4*>(&bb[4]) = *reinterpret_cast<float4*>(&Bs[kk][64 + tn * 4]);
#pragma unroll
            for (int u = 0; u < 8; ++u)
#pragma unroll
                for (int v = 0; v < 8; ++v) acc[u][v] += a[u] * bb[v];
        }
    }

    float bo[4], bsv[4];
#pragma unroll
    for (int v = 0; v < 4; ++v) {
        bo[v]  = g_bfin[tn * 4 + v];
        bsv[v] = g_bfin[64 + tn * 4 + v];
    }
#pragma unroll
    for (int u = 0; u < 8; ++u) {
        size_t base = (size_t)(r0 + tm * 8 + u) * CC;
        float4 xr = *reinterpret_cast<const float4*>(x + base + tn * 4);
        float4 o1, o2;
        o1.x = acc[u][0] + bo[0] + xr.x;
        o1.y = acc[u][1] + bo[1] + xr.y;
        o1.z = acc[u][2] + bo[2] + xr.z;
        o1.w = acc[u][3] + bo[3] + xr.w;
        o2.x = acc[u][4] + bsv[0];
        o2.y = acc[u][5] + bsv[1];
        o2.z = acc[u][6] + bsv[2];
        o2.w = acc[u][7] + bsv[3];
        *reinterpret_cast<float4*>(&out[base + tn * 4]) = o1;                 // out tensor
        *reinterpret_cast<float4*>(&out[(size_t)HN + base + tn * 4]) = o2;    // skip tensor
    }
}

// ---------------- launch ------------------------------------------------------
extern "C" void kernel_launch(void* const* d_in, const int* in_sizes, int n_in,
                              void* d_out, int out_size) {
    P p;
    p.x   = (const float*)d_in[0];
    p.adj = (const float*)d_in[1];
    for (int b = 0; b < 4; ++b) {
        p.wf[b] = (const float*)d_in[2 + b * 4 + 0];
        p.bf[b] = (const float*)d_in[2 + b * 4 + 1];
        p.wg[b] = (const float*)d_in[2 + b * 4 + 2];
        p.bg[b] = (const float*)d_in[2 + b * 4 + 3];
    }
    p.Wgf = (const float*)d_in[18];
    p.bgf = (const float*)d_in[19];
    p.Wgr = (const float*)d_in[20];
    p.bgr = (const float*)d_in[21];
    p.Ws  = (const float*)d_in[22];
    p.bs  = (const float*)d_in[23];
    float* out = (float*)d_out;

    prep_adj<<<NN, 256>>>(p.adj);
    prep_w<<<385, 256>>>(p);

    dim3 gc(4, BT);
    conv_kernel<<<gc, 256>>>(p.x);

    dim3 gh(2, BT);
    hop_kernel<<<gh, 256>>>(0, 0);
    hop_kernel<<<gh, 256>>>(0, 1);
    hop_kernel<<<gh, 256>>>(1, 0);
    hop_kernel<<<gh, 256>>>(1, 1);

    final_kernel<<<BTN / 128, 256>>>(p.x, out);
}

// round 2
// speedup vs baseline: 5.0438x; 5.0438x over previous
#include <cuda_runtime.h>
#include <cstdint>
#include <math.h>

#define NNODE 512
#define CC 64
#define BT 2048           // B*T
#define BTN 1048576
#define HN 67108864       // BTN*CC
#define ALPHA 0.05f

// ---------------- device scratch ---------------------------------------------
__device__ float g_h  [HN];   // fp32 conv output (for alpha-blend + reference path)
__device__ float g_ht [HN];   // tf32 copy of h
__device__ float g_h1f[HN];   // tf32 hop outputs
__device__ float g_h2f[HN];
__device__ float g_h1r[HN];
__device__ float g_h2r[HN];
__device__ float g_xt [HN];   // tf32 copy of x
__device__ float g_Af [NNODE*NNODE];   // tf32 row-normalized adj
__device__ float g_Ar [NNODE*NNODE];
__device__ float g_Wpad[7*64*128];     // tf32, cols interleaved (2j=filter j, 2j+1=gate j)
__device__ float g_bconv[128];         // fp32, same interleave
__device__ float g_Wfin[320*128];      // tf32 [k][c] c<64 out, c>=64 skip
__device__ float g_bfin[128];          // fp32

struct P {
    const float* x; const float* adj;
    const float* wf[4]; const float* bf[4];
    const float* wg[4]; const float* bg[4];
    const float* Wgf; const float* bgf;
    const float* Wgr; const float* bgr;
    const float* Ws;  const float* bs;
};

// ---------------- small helpers ----------------------------------------------
__device__ __forceinline__ float tf32r(float x) {
    uint32_t u;
    asm("cvt.rna.tf32.f32 %0, %1;" : "=r"(u) : "r"(__float_as_uint(x)));
    return __uint_as_float(u);
}

__device__ __forceinline__ void mma8(float* d, const uint32_t* a, const uint32_t* b) {
    asm volatile(
        "mma.sync.aligned.m16n8k8.row.col.f32.tf32.tf32.f32 "
        "{%0,%1,%2,%3}, {%4,%5,%6,%7}, {%8,%9}, {%0,%1,%2,%3};\n"
        : "+f"(d[0]), "+f"(d[1]), "+f"(d[2]), "+f"(d[3])
        : "r"(a[0]), "r"(a[1]), "r"(a[2]), "r"(a[3]), "r"(b[0]), "r"(b[1]));
}

__device__ __forceinline__ void cpa16(uint32_t dst, const float* src) {
    asm volatile("cp.async.cg.shared.global [%0], [%1], 16;" :: "r"(dst), "l"(src));
}
__device__ __forceinline__ void cp_commit() { asm volatile("cp.async.commit_group;"); }
template<int N> __device__ __forceinline__ void cp_wait() {
    asm volatile("cp.async.wait_group %0;" :: "n"(N) : "memory");
}
__device__ __forceinline__ uint32_t s2u(const void* p) {
    return (uint32_t)__cvta_generic_to_shared(p);
}

// ---------------- prep: adjacencies (tf32) ------------------------------------
__global__ void prep_adj(const float* __restrict__ adj) {
    int n = blockIdx.x, tid = threadIdx.x;
    __shared__ float red[256];
    float s1 = 0.f, s2 = 0.f;
    for (int m = tid; m < NNODE; m += 256) {
        s1 += adj[n * NNODE + m];
        s2 += adj[m * NNODE + n];
    }
    red[tid] = s1; __syncthreads();
    for (int k = 128; k; k >>= 1) { if (tid < k) red[tid] += red[tid + k]; __syncthreads(); }
    float inv1 = 1.f / fmaxf(red[0] + 1.f, 1e-9f);
    __syncthreads();
    red[tid] = s2; __syncthreads();
    for (int k = 128; k; k >>= 1) { if (tid < k) red[tid] += red[tid + k]; __syncthreads(); }
    float inv2 = 1.f / fmaxf(red[0] + 1.f, 1e-9f);
    for (int m = tid; m < NNODE; m += 256) {
        g_Af[n * NNODE + m] = tf32r((adj[n * NNODE + m] + (m == n ? 1.f : 0.f)) * inv1);
        g_Ar[n * NNODE + m] = tf32r((adj[m * NNODE + n] + (m == n ? 1.f : 0.f)) * inv2);
    }
}

// ---------------- prep: weights ------------------------------------------------
__global__ void prep_w(P p) {
    int idx = blockIdx.x * blockDim.x + threadIdx.x;
    const int KR[4] = {2, 3, 6, 7};
    if (idx < 57344) {
        int d = idx / 8192, rem = idx % 8192;
        int cin = rem / 128, cp = rem % 128;
        int j = cp >> 1, gsel = cp & 1;
        int i = j >> 4, r = j & 15;
        int k = KR[i], jj = k - 1 - d;
        float v = 0.f;
        if (jj >= 0) {
            const float* w = gsel ? p.wg[i] : p.wf[i];
            v = w[(jj * 64 + cin) * 16 + r];
        }
        g_Wpad[(d * 64 + cin) * 128 + cp] = tf32r(v);
        return;
    }
    int i2 = idx - 57344;
    if (i2 < 128) {
        int j = i2 >> 1, gsel = i2 & 1;
        int i = j >> 4, r = j & 15;
        g_bconv[i2] = gsel ? p.bg[i][r] : p.bf[i][r];
        return;
    }
    int i3 = idx - 57472;
    if (i3 < 40960) {
        int k = i3 / 128, c = i3 % 128;
        float v = 0.f;
        if (c < 64) {
            int s = k >> 6, kk = k & 63;
            if      (s == 0) v = p.Wgf[kk * 64 + c] + p.Wgr[kk * 64 + c];
            else if (s == 1) v = p.Wgf[( 64 + kk) * 64 + c];
            else if (s == 2) v = p.Wgf[(128 + kk) * 64 + c];
            else if (s == 3) v = p.Wgr[( 64 + kk) * 64 + c];
            else             v = p.Wgr[(128 + kk) * 64 + c];
        } else {
            if (k < 64) v = p.Ws[k * 64 + (c - 64)];
        }
        g_Wfin[i3] = tf32r(v);
        return;
    }
    int i4 = idx - 98432;
    if (i4 >= 0 && i4 < 128)
        g_bfin[i4] = (i4 < 64) ? (p.bgf[i4] + p.bgr[i4]) : p.bs[i4 - 64];
}

// ---------------- prep: tf32 copy of x ----------------------------------------
__global__ void prep_xt(const float* __restrict__ x) {
    int i = blockIdx.x * blockDim.x + threadIdx.x;   // float4 index
    float4 v = *reinterpret_cast<const float4*>(x + (size_t)i * 4);
    v.x = tf32r(v.x); v.y = tf32r(v.y); v.z = tf32r(v.z); v.w = tf32r(v.w);
    *reinterpret_cast<float4*>(g_xt + (size_t)i * 4) = v;
}

// =============================================================================
// conv: h = tanh(f)*sigmoid(g), shift-GEMM, CTA 128x128, K = 2*min(t+1,7)*32
// =============================================================================
#define CONV_AS (2 * 128 * 36)
#define CONV_BS (2 * 32 * 136)
__global__ __launch_bounds__(256, 2) void conv_mma() {
    extern __shared__ float smem[];
    float* As = smem;                 // [2][128][36]
    float* Bs = smem + CONV_AS;       // [2][32][136]
    const int bt = blockIdx.y;
    const int t  = bt & 255;
    const int n0 = blockIdx.x * 128;
    const int tid = threadIdx.x;
    const int w = tid >> 5, lane = tid & 31;
    const int grp = lane >> 2, q = lane & 3;
    const int wM = w & 1, wN = w >> 1;
    const uint32_t sA = s2u(As), sB = s2u(Bs);
    const int NC = 2 * ((t + 1 < 7) ? (t + 1) : 7);

    float acc[4][4][4];
#pragma unroll
    for (int a = 0; a < 4; ++a)
#pragma unroll
        for (int b = 0; b < 4; ++b)
#pragma unroll
            for (int c = 0; c < 4; ++c) acc[a][b][c] = 0.f;

#define CONV_ISSUE(kc, buf) {                                                   \
        int d_ = (kc) >> 1, c0_ = ((kc) & 1) * 32;                              \
        const float* xb = g_xt + ((size_t)(bt - d_) * NNODE + n0) * CC + c0_;   \
        _Pragma("unroll")                                                       \
        for (int i = 0; i < 4; ++i) {                                           \
            int li = tid + i * 256, row = li >> 3, c4 = li & 7;                 \
            cpa16(sA + (((buf) * 128 + row) * 36 + c4 * 4) * 4,                 \
                  xb + (size_t)row * CC + c4 * 4);                              \
        }                                                                       \
        const float* wb = g_Wpad + (d_ * 64 + c0_) * 128;                       \
        _Pragma("unroll")                                                       \
        for (int i = 0; i < 4; ++i) {                                           \
            int li = tid + i * 256, k = li >> 5, c4 = li & 31;                  \
            cpa16(sB + (((buf) * 32 + k) * 136 + c4 * 4) * 4,                   \
                  wb + k * 128 + c4 * 4);                                       \
        }                                                                       \
        cp_commit();                                                            \
    }

    CONV_ISSUE(0, 0);
    for (int kc = 0; kc < NC; ++kc) {
        if (kc + 1 < NC) { CONV_ISSUE(kc + 1, (kc + 1) & 1); cp_wait<1>(); }
        else cp_wait<0>();
        __syncthreads();
        const float* Ab = As + (kc & 1) * 128 * 36;
        const float* Bb = Bs + (kc & 1) * 32 * 136;
#pragma unroll
        for (int ks = 0; ks < 4; ++ks) {
            uint32_t af[4][4], bf[4][2];
#pragma unroll
            for (int mt = 0; mt < 4; ++mt) {
                const float* pA = Ab + (wM * 64 + mt * 16 + grp) * 36 + ks * 8 + q;
                af[mt][0] = __float_as_uint(pA[0]);
                af[mt][1] = __float_as_uint(pA[8 * 36]);
                af[mt][2] = __float_as_uint(pA[4]);
                af[mt][3] = __float_as_uint(pA[8 * 36 + 4]);
            }
#pragma unroll
            for (int nt = 0; nt < 4; ++nt) {
                const float* pB = Bb + (ks * 8 + q) * 136 + wN * 32 + nt * 8 + grp;
                bf[nt][0] = __float_as_uint(pB[0]);
                bf[nt][1] = __float_as_uint(pB[4 * 136]);
            }
#pragma unroll
            for (int mt = 0; mt < 4; ++mt)
#pragma unroll
                for (int nt = 0; nt < 4; ++nt)
                    mma8(acc[mt][nt], af[mt], bf[nt]);
        }
        __syncthreads();
    }

    // epilogue: gated activation, cols interleaved (2j=filter, 2j+1=gate)
#pragma unroll
    for (int mt = 0; mt < 4; ++mt) {
#pragma unroll
        for (int half = 0; half < 2; ++half) {
            int row = n0 + wM * 64 + mt * 16 + grp + half * 8;
            size_t rb = ((size_t)bt * NNODE + row) * CC;
#pragma unroll
            for (int nt = 0; nt < 4; ++nt) {
                int j = wN * 16 + nt * 4 + q;
                float f = acc[mt][nt][half * 2 + 0] + g_bconv[2 * j];
                float g = acc[mt][nt][half * 2 + 1] + g_bconv[2 * j + 1];
                float th = 1.f - 2.f / (__expf(2.f * f) + 1.f);
                float sg = 1.f / (1.f + __expf(-g));
                float h = th * sg;
                g_h [rb + j] = h;
                g_ht[rb + j] = tf32r(h);
            }
        }
    }
}

// =============================================================================
// hop: hout = tf32(alpha*h + (1-alpha)*A@hin), CTA 256x64, K=512
// =============================================================================
#define HOP_AS (2 * 256 * 36)
#define HOP_BS (2 * 32 * 72)
__global__ __launch_bounds__(256, 2) void hop_mma(int dir, int hop) {
    extern __shared__ float smem[];
    float* As = smem;                 // [2][256][36]
    float* Bs = smem + HOP_AS;        // [2][32][72]
    const float* Aadj = dir ? g_Ar : g_Af;
    const float* hin  = hop ? (dir ? g_h1r : g_h1f) : g_ht;
    float* hout       = hop ? (dir ? g_h2r : g_h2f) : (dir ? g_h1r : g_h1f);

    const int bt = blockIdx.y;
    const int n0 = blockIdx.x * 256;
    const int tid = threadIdx.x;
    const int w = tid >> 5, lane = tid & 31;
    const int grp = lane >> 2, q = lane & 3;
    const int wM = w & 3, wN = w >> 2;
    const uint32_t sA = s2u(As), sB = s2u(Bs);
    const float* hb = hin + (size_t)bt * NNODE * CC;

    float acc[4][4][4];
#pragma unroll
    for (int a = 0; a < 4; ++a)
#pragma unroll
        for (int b = 0; b < 4; ++b)
#pragma unroll
            for (int c = 0; c < 4; ++c) acc[a][b][c] = 0.f;

#define HOP_ISSUE(kc, buf) {                                                    \
        _Pragma("unroll")                                                       \
        for (int i = 0; i < 8; ++i) {                                           \
            int li = tid + i * 256, row = li >> 3, c4 = li & 7;                 \
            cpa16(sA + (((buf) * 256 + row) * 36 + c4 * 4) * 4,                 \
                  Aadj + (size_t)(n0 + row) * NNODE + (kc) * 32 + c4 * 4);      \
        }                                                                       \
        _Pragma("unroll")                                                       \
        for (int i = 0; i < 2; ++i) {                                           \
            int li = tid + i * 256, k = li >> 4, f4 = li & 15;                  \
            cpa16(sB + (((buf) * 32 + k) * 72 + f4 * 4) * 4,                    \
                  hb + (size_t)((kc) * 32 + k) * CC + f4 * 4);                  \
        }                                                                       \
        cp_commit();                                                            \
    }

    HOP_ISSUE(0, 0);
    for (int kc = 0; kc < 16; ++kc) {
        if (kc + 1 < 16) { HOP_ISSUE(kc + 1, (kc + 1) & 1); cp_wait<1>(); }
        else cp_wait<0>();
        __syncthreads();
        const float* Ab = As + (kc & 1) * 256 * 36;
        const float* Bb = Bs + (kc & 1) * 32 * 72;
#pragma unroll
        for (int ks = 0; ks < 4; ++ks) {
            uint32_t af[4][4], bf[4][2];
#pragma unroll
            for (int mt = 0; mt < 4; ++mt) {
                const float* pA = Ab + (wM * 64 + mt * 16 + grp) * 36 + ks * 8 + q;
                af[mt][0] = __float_as_uint(pA[0]);
                af[mt][1] = __float_as_uint(pA[8 * 36]);
                af[mt][2] = __float_as_uint(pA[4]);
                af[mt][3] = __float_as_uint(pA[8 * 36 + 4]);
            }
#pragma unroll
            for (int nt = 0; nt < 4; ++nt) {
                const float* pB = Bb + (ks * 8 + q) * 72 + wN * 32 + nt * 8 + grp;
                bf[nt][0] = __float_as_uint(pB[0]);
                bf[nt][1] = __float_as_uint(pB[4 * 72]);
            }
#pragma unroll
            for (int mt = 0; mt < 4; ++mt)
#pragma unroll
                for (int nt = 0; nt < 4; ++nt)
                    mma8(acc[mt][nt], af[mt], bf[nt]);
        }
        __syncthreads();
    }

    const float om = 1.f - ALPHA;
#pragma unroll
    for (int mt = 0; mt < 4; ++mt) {
#pragma unroll
        for (int half = 0; half < 2; ++half) {
            int row = n0 + wM * 64 + mt * 16 + grp + half * 8;
            size_t rb = ((size_t)bt * NNODE + row) * CC + wN * 32 + 2 * q;
#pragma unroll
            for (int nt = 0; nt < 4; ++nt) {
                size_t a = rb + nt * 8;
                float d0 = acc[mt][nt][half * 2 + 0];
                float d1 = acc[mt][nt][half * 2 + 1];
                float2 h0 = *reinterpret_cast<const float2*>(&g_h[a]);
                float o0 = tf32r(ALPHA * h0.x + om * d0);
                float o1 = tf32r(ALPHA * h0.y + om * d1);
                *reinterpret_cast<float2*>(&hout[a]) = make_float2(o0, o1);
            }
        }
    }
}

// =============================================================================
// final: out = concat5@Wfin[:,:64]+b+x ; skip = h@Ws+bs. CTA 128x128, K=320
// =============================================================================
__global__ __launch_bounds__(256, 2) void final_mma(const float* __restrict__ x,
                                                    float* __restrict__ out) {
    extern __shared__ float smem[];
    float* As = smem;                 // [2][128][36]
    float* Bs = smem + CONV_AS;       // [2][32][136]
    const int r0 = blockIdx.x * 128;
    const int tid = threadIdx.x;
    const int w = tid >> 5, lane = tid & 31;
    const int grp = lane >> 2, q = lane & 3;
    const int wM = w & 1, wN = w >> 1;
    const uint32_t sA = s2u(As), sB = s2u(Bs);

    float acc[4][4][4];
#pragma unroll
    for (int a = 0; a < 4; ++a)
#pragma unroll
        for (int b = 0; b < 4; ++b)
#pragma unroll
            for (int c = 0; c < 4; ++c) acc[a][b][c] = 0.f;

    const float* const srcs[5] = {g_ht, g_h1f, g_h2f, g_h1r, g_h2r};

#define FIN_ISSUE(kc, buf) {                                                    \
        const float* sp = srcs[(kc) >> 1] + ((kc) & 1) * 32;                    \
        _Pragma("unroll")                                                       \
        for (int i = 0; i < 4; ++i) {                                           \
            int li = tid + i * 256, row = li >> 3, c4 = li & 7;                 \
            cpa16(sA + (((buf) * 128 + row) * 36 + c4 * 4) * 4,                 \
                  sp + (size_t)(r0 + row) * CC + c4 * 4);                       \
        }                                                                       \
        const float* wb = g_Wfin + (kc) * 32 * 128;                             \
        _Pragma("unroll")                                                       \
        for (int i = 0; i < 4; ++i) {                                           \
            int li = tid + i * 256, k = li >> 5, c4 = li & 31;                  \
            cpa16(sB + (((buf) * 32 + k) * 136 + c4 * 4) * 4,                   \
                  wb + k * 128 + c4 * 4);                                       \
        }                                                                       \
        cp_commit();                                                            \
    }

    FIN_ISSUE(0, 0);
    for (int kc = 0; kc < 10; ++kc) {
        if (kc + 1 < 10) { FIN_ISSUE(kc + 1, (kc + 1) & 1); cp_wait<1>(); }
        else cp_wait<0>();
        __syncthreads();
        const float* Ab = As + (kc & 1) * 128 * 36;
        const float* Bb = Bs + (kc & 1) * 32 * 136;
#pragma unroll
        for (int ks = 0; ks < 4; ++ks) {
            uint32_t af[4][4], bf[4][2];
#pragma unroll
            for (int mt = 0; mt < 4; ++mt) {
                const float* pA = Ab + (wM * 64 + mt * 16 + grp) * 36 + ks * 8 + q;
                af[mt][0] = __float_as_uint(pA[0]);
                af[mt][1] = __float_as_uint(pA[8 * 36]);
                af[mt][2] = __float_as_uint(pA[4]);
                af[mt][3] = __float_as_uint(pA[8 * 36 + 4]);
            }
#pragma unroll
            for (int nt = 0; nt < 4; ++nt) {
                const float* pB = Bb + (ks * 8 + q) * 136 + wN * 32 + nt * 8 + grp;
                bf[nt][0] = __float_as_uint(pB[0]);
                bf[nt][1] = __float_as_uint(pB[4 * 136]);
            }
#pragma unroll
            for (int mt = 0; mt < 4; ++mt)
#pragma unroll
                for (int nt = 0; nt < 4; ++nt)
                    mma8(acc[mt][nt], af[mt], bf[nt]);
        }
        __syncthreads();
    }

#pragma unroll
    for (int mt = 0; mt < 4; ++mt) {
#pragma unroll
        for (int half = 0; half < 2; ++half) {
            int row = r0 + wM * 64 + mt * 16 + grp + half * 8;
#pragma unroll
            for (int nt = 0; nt < 4; ++nt) {
                int col = wN * 32 + nt * 8 + 2 * q;
                float d0 = acc[mt][nt][half * 2 + 0] + g_bfin[col];
                float d1 = acc[mt][nt][half * 2 + 1] + g_bfin[col + 1];
                if (wN < 2) {  // out half: + residual x
                    size_t a = (size_t)row * CC + col;
                    float2 xr = *reinterpret_cast<const float2*>(&x[a]);
                    *reinterpret_cast<float2*>(&out[a]) =
                        make_float2(d0 + xr.x, d1 + xr.y);
                } else {       // skip half
                    size_t a = (size_t)HN + (size_t)row * CC + (col - 64);
                    *reinterpret_cast<float2*>(&out[a]) = make_float2(d0, d1);
                }
            }
        }
    }
}

// ---------------- launch ------------------------------------------------------
extern "C" void kernel_launch(void* const* d_in, const int* in_sizes, int n_in,
                              void* d_out, int out_size) {
    P p;
    p.x   = (const float*)d_in[0];
    p.adj = (const float*)d_in[1];
    for (int b = 0; b < 4; ++b) {
        p.wf[b] = (const float*)d_in[2 + b * 4 + 0];
        p.bf[b] = (const float*)d_in[2 + b * 4 + 1];
        p.wg[b] = (const float*)d_in[2 + b * 4 + 2];
        p.bg[b] = (const float*)d_in[2 + b * 4 + 3];
    }
    p.Wgf = (const float*)d_in[18];
    p.bgf = (const float*)d_in[19];
    p.Wgr = (const float*)d_in[20];
    p.bgr = (const float*)d_in[21];
    p.Ws  = (const float*)d_in[22];
    p.bs  = (const float*)d_in[23];
    float* out = (float*)d_out;

    const int convSmem = (CONV_AS + CONV_BS) * 4;   // 71680 B
    const int hopSmem  = (HOP_AS + HOP_BS) * 4;     // 92160 B
    cudaFuncSetAttribute(conv_mma,  cudaFuncAttributeMaxDynamicSharedMemorySize, convSmem);
    cudaFuncSetAttribute(hop_mma,   cudaFuncAttributeMaxDynamicSharedMemorySize, hopSmem);
    cudaFuncSetAttribute(final_mma, cudaFuncAttributeMaxDynamicSharedMemorySize, convSmem);

    prep_adj<<<NNODE, 256>>>(p.adj);
    prep_w<<<385, 256>>>(p);
    prep_xt<<<HN / 4 / 256, 256>>>(p.x);

    dim3 gc(4, BT);
    conv_mma<<<gc, 256, convSmem>>>();

    dim3 gh(2, BT);
    hop_mma<<<gh, 256, hopSmem>>>(0, 0);
    hop_mma<<<gh, 256, hopSmem>>>(0, 1);
    hop_mma<<<gh, 256, hopSmem>>>(1, 0);
    hop_mma<<<gh, 256, hopSmem>>>(1, 1);

    final_mma<<<BTN / 128, 256, convSmem>>>(p.x, out);
}

// round 3
// speedup vs baseline: 5.0457x; 1.0004x over previous
#include <cuda_runtime.h>
#include <cstdint>
#include <math.h>

#define NNODE 512
#define CC 64
#define BT 2048           // B*T
#define BTN 1048576
#define HN 67108864       // BTN*CC
#define ALPHA 0.05f

// ---------------- device scratch ---------------------------------------------
__device__ float g_h  [HN];   // fp32 conv output (for alpha-blend + reference path)
__device__ float g_ht [HN];   // tf32 copy of h
__device__ float g_h1f[HN];   // tf32 hop outputs
__device__ float g_h2f[HN];
__device__ float g_h1r[HN];
__device__ float g_h2r[HN];
__device__ float g_xt [HN];   // tf32 copy of x
__device__ float g_Af [NNODE*NNODE];   // tf32 row-normalized adj
__device__ float g_Ar [NNODE*NNODE];
__device__ float g_Wpad[7*64*128];     // tf32, cols interleaved (2j=filter j, 2j+1=gate j)
__device__ float g_bconv[128];         // fp32, same interleave
__device__ float g_Wfin[320*128];      // tf32 [k][c] c<64 out, c>=64 skip
__device__ float g_bfin[128];          // fp32

struct P {
    const float* x; const float* adj;
    const float* wf[4]; const float* bf[4];
    const float* wg[4]; const float* bg[4];
    const float* Wgf; const float* bgf;
    const float* Wgr; const float* bgr;
    const float* Ws;  const float* bs;
};

// ---------------- small helpers ----------------------------------------------
__device__ __forceinline__ float tf32r(float x) {
    uint32_t u;
    asm("cvt.rna.tf32.f32 %0, %1;" : "=r"(u) : "r"(__float_as_uint(x)));
    return __uint_as_float(u);
}

__device__ __forceinline__ void mma8(float* d, const uint32_t* a, const uint32_t* b) {
    asm volatile(
        "mma.sync.aligned.m16n8k8.row.col.f32.tf32.tf32.f32 "
        "{%0,%1,%2,%3}, {%4,%5,%6,%7}, {%8,%9}, {%0,%1,%2,%3};\n"
        : "+f"(d[0]), "+f"(d[1]), "+f"(d[2]), "+f"(d[3])
        : "r"(a[0]), "r"(a[1]), "r"(a[2]), "r"(a[3]), "r"(b[0]), "r"(b[1]));
}

__device__ __forceinline__ void cpa16(uint32_t dst, const float* src) {
    asm volatile("cp.async.cg.shared.global [%0], [%1], 16;" :: "r"(dst), "l"(src));
}
__device__ __forceinline__ void cp_commit() { asm volatile("cp.async.commit_group;"); }
template<int N> __device__ __forceinline__ void cp_wait() {
    asm volatile("cp.async.wait_group %0;" :: "n"(N) : "memory");
}
__device__ __forceinline__ uint32_t s2u(const void* p) {
    return (uint32_t)__cvta_generic_to_shared(p);
}

// ---------------- prep: adjacencies (tf32) ------------------------------------
__global__ void prep_adj(const float* __restrict__ adj) {
    int n = blockIdx.x, tid = threadIdx.x;
    __shared__ float red[256];
    float s1 = 0.f, s2 = 0.f;
    for (int m = tid; m < NNODE; m += 256) {
        s1 += adj[n * NNODE + m];
        s2 += adj[m * NNODE + n];
    }
    red[tid] = s1; __syncthreads();
    for (int k = 128; k; k >>= 1) { if (tid < k) red[tid] += red[tid + k]; __syncthreads(); }
    float inv1 = 1.f / fmaxf(red[0] + 1.f, 1e-9f);
    __syncthreads();
    red[tid] = s2; __syncthreads();
    for (int k = 128; k; k >>= 1) { if (tid < k) red[tid] += red[tid + k]; __syncthreads(); }
    float inv2 = 1.f / fmaxf(red[0] + 1.f, 1e-9f);
    for (int m = tid; m < NNODE; m += 256) {
        g_Af[n * NNODE + m] = tf32r((adj[n * NNODE + m] + (m == n ? 1.f : 0.f)) * inv1);
        g_Ar[n * NNODE + m] = tf32r((adj[m * NNODE + n] + (m == n ? 1.f : 0.f)) * inv2);
    }
}

// ---------------- prep: weights ------------------------------------------------
__global__ void prep_w(P p) {
    int idx = blockIdx.x * blockDim.x + threadIdx.x;
    const int KR[4] = {2, 3, 6, 7};
    if (idx < 57344) {
        int d = idx / 8192, rem = idx % 8192;
        int cin = rem / 128, cp = rem % 128;
        int j = cp >> 1, gsel = cp & 1;
        int i = j >> 4, r = j & 15;
        int k = KR[i], jj = k - 1 - d;
        float v = 0.f;
        if (jj >= 0) {
            const float* w = gsel ? p.wg[i] : p.wf[i];
            v = w[(jj * 64 + cin) * 16 + r];
        }
        g_Wpad[(d * 64 + cin) * 128 + cp] = tf32r(v);
        return;
    }
    int i2 = idx - 57344;
    if (i2 < 128) {
        int j = i2 >> 1, gsel = i2 & 1;
        int i = j >> 4, r = j & 15;
        g_bconv[i2] = gsel ? p.bg[i][r] : p.bf[i][r];
        return;
    }
    int i3 = idx - 57472;
    if (i3 < 40960) {
        int k = i3 / 128, c = i3 % 128;
        float v = 0.f;
        if (c < 64) {
            int s = k >> 6, kk = k & 63;
            if      (s == 0) v = p.Wgf[kk * 64 + c] + p.Wgr[kk * 64 + c];
            else if (s == 1) v = p.Wgf[( 64 + kk) * 64 + c];
            else if (s == 2) v = p.Wgf[(128 + kk) * 64 + c];
            else if (s == 3) v = p.Wgr[( 64 + kk) * 64 + c];
            else             v = p.Wgr[(128 + kk) * 64 + c];
        } else {
            if (k < 64) v = p.Ws[k * 64 + (c - 64)];
        }
        g_Wfin[i3] = tf32r(v);
        return;
    }
    int i4 = idx - 98432;
    if (i4 >= 0 && i4 < 128)
        g_bfin[i4] = (i4 < 64) ? (p.bgf[i4] + p.bgr[i4]) : p.bs[i4 - 64];
}

// ---------------- prep: tf32 copy of x ----------------------------------------
__global__ void prep_xt(const float* __restrict__ x) {
    int i = blockIdx.x * blockDim.x + threadIdx.x;   // float4 index
    float4 v = *reinterpret_cast<const float4*>(x + (size_t)i * 4);
    v.x = tf32r(v.x); v.y = tf32r(v.y); v.z = tf32r(v.z); v.w = tf32r(v.w);
    *reinterpret_cast<float4*>(g_xt + (size_t)i * 4) = v;
}

// =============================================================================
// conv: h = tanh(f)*sigmoid(g), shift-GEMM, CTA 128x128, K = 2*min(t+1,7)*32
// =============================================================================
#define CONV_AS (2 * 128 * 36)
#define CONV_BS (2 * 32 * 136)
__global__ __launch_bounds__(256, 2) void conv_mma() {
    extern __shared__ float smem[];
    float* As = smem;                 // [2][128][36]
    float* Bs = smem + CONV_AS;       // [2][32][136]
    const int bt = blockIdx.y;
    const int t  = bt & 255;
    const int n0 = blockIdx.x * 128;
    const int tid = threadIdx.x;
    const int w = tid >> 5, lane = tid & 31;
    const int grp = lane >> 2, q = lane & 3;
    const int wM = w & 1, wN = w >> 1;
    const uint32_t sA = s2u(As), sB = s2u(Bs);
    const int NC = 2 * ((t + 1 < 7) ? (t + 1) : 7);

    float acc[4][4][4];
#pragma unroll
    for (int a = 0; a < 4; ++a)
#pragma unroll
        for (int b = 0; b < 4; ++b)
#pragma unroll
            for (int c = 0; c < 4; ++c) acc[a][b][c] = 0.f;

#define CONV_ISSUE(kc, buf) {                                                   \
        int d_ = (kc) >> 1, c0_ = ((kc) & 1) * 32;                              \
        const float* xb = g_xt + ((size_t)(bt - d_) * NNODE + n0) * CC + c0_;   \
        _Pragma("unroll")                                                       \
        for (int i = 0; i < 4; ++i) {                                           \
            int li = tid + i * 256, row = li >> 3, c4 = li & 7;                 \
            cpa16(sA + (((buf) * 128 + row) * 36 + c4 * 4) * 4,                 \
                  xb + (size_t)row * CC + c4 * 4);                              \
        }                                                                       \
        const float* wb = g_Wpad + (d_ * 64 + c0_) * 128;                       \
        _Pragma("unroll")                                                       \
        for (int i = 0; i < 4; ++i) {                                           \
            int li = tid + i * 256, k = li >> 5, c4 = li & 31;                  \
            cpa16(sB + (((buf) * 32 + k) * 136 + c4 * 4) * 4,                   \
                  wb + k * 128 + c4 * 4);                                       \
        }                                                                       \
        cp_commit();                                                            \
    }

    CONV_ISSUE(0, 0);
    for (int kc = 0; kc < NC; ++kc) {
        if (kc + 1 < NC) { CONV_ISSUE(kc + 1, (kc + 1) & 1); cp_wait<1>(); }
        else cp_wait<0>();
        __syncthreads();
        const float* Ab = As + (kc & 1) * 128 * 36;
        const float* Bb = Bs + (kc & 1) * 32 * 136;
#pragma unroll
        for (int ks = 0; ks < 4; ++ks) {
            uint32_t af[4][4], bf[4][2];
#pragma unroll
            for (int mt = 0; mt < 4; ++mt) {
                const float* pA = Ab + (wM * 64 + mt * 16 + grp) * 36 + ks * 8 + q;
                af[mt][0] = __float_as_uint(pA[0]);
                af[mt][1] = __float_as_uint(pA[8 * 36]);
                af[mt][2] = __float_as_uint(pA[4]);
                af[mt][3] = __float_as_uint(pA[8 * 36 + 4]);
            }
#pragma unroll
            for (int nt = 0; nt < 4; ++nt) {
                const float* pB = Bb + (ks * 8 + q) * 136 + wN * 32 + nt * 8 + grp;
                bf[nt][0] = __float_as_uint(pB[0]);
                bf[nt][1] = __float_as_uint(pB[4 * 136]);
            }
#pragma unroll
            for (int mt = 0; mt < 4; ++mt)
#pragma unroll
                for (int nt = 0; nt < 4; ++nt)
                    mma8(acc[mt][nt], af[mt], bf[nt]);
        }
        __syncthreads();
    }

    // epilogue: gated activation, cols interleaved (2j=filter, 2j+1=gate)
#pragma unroll
    for (int mt = 0; mt < 4; ++mt) {
#pragma unroll
        for (int half = 0; half < 2; ++half) {
            int row = n0 + wM * 64 + mt * 16 + grp + half * 8;
            size_t rb = ((size_t)bt * NNODE + row) * CC;
#pragma unroll
            for (int nt = 0; nt < 4; ++nt) {
                int j = wN * 16 + nt * 4 + q;
                float f = acc[mt][nt][half * 2 + 0] + g_bconv[2 * j];
                float g = acc[mt][nt][half * 2 + 1] + g_bconv[2 * j + 1];
                float th = 1.f - 2.f / (__expf(2.f * f) + 1.f);
                float sg = 1.f / (1.f + __expf(-g));
                float h = th * sg;
                g_h [rb + j] = h;
                g_ht[rb + j] = tf32r(h);
            }
        }
    }
}

// =============================================================================
// hop: hout = tf32(alpha*h + (1-alpha)*A@hin), CTA 256x64, K=512
// =============================================================================
#define HOP_AS (2 * 256 * 36)
#define HOP_BS (2 * 32 * 72)
__global__ __launch_bounds__(256, 2) void hop_mma(int dir, int hop) {
    extern __shared__ float smem[];
    float* As = smem;                 // [2][256][36]
    float* Bs = smem + HOP_AS;        // [2][32][72]
    const float* Aadj = dir ? g_Ar : g_Af;
    const float* hin  = hop ? (dir ? g_h1r : g_h1f) : g_ht;
    float* hout       = hop ? (dir ? g_h2r : g_h2f) : (dir ? g_h1r : g_h1f);

    const int bt = blockIdx.y;
    const int n0 = blockIdx.x * 256;
    const int tid = threadIdx.x;
    const int w = tid >> 5, lane = tid & 31;
    const int grp = lane >> 2, q = lane & 3;
    const int wM = w & 3, wN = w >> 2;
    const uint32_t sA = s2u(As), sB = s2u(Bs);
    const float* hb = hin + (size_t)bt * NNODE * CC;

    float acc[4][4][4];
#pragma unroll
    for (int a = 0; a < 4; ++a)
#pragma unroll
        for (int b = 0; b < 4; ++b)
#pragma unroll
            for (int c = 0; c < 4; ++c) acc[a][b][c] = 0.f;

#define HOP_ISSUE(kc, buf) {                                                    \
        _Pragma("unroll")                                                       \
        for (int i = 0; i < 8; ++i) {                                           \
            int li = tid + i * 256, row = li >> 3, c4 = li & 7;                 \
            cpa16(sA + (((buf) * 256 + row) * 36 + c4 * 4) * 4,                 \
                  Aadj + (size_t)(n0 + row) * NNODE + (kc) * 32 + c4 * 4);      \
        }                                                                       \
        _Pragma("unroll")                                                       \
        for (int i = 0; i < 2; ++i) {                                           \
            int li = tid + i * 256, k = li >> 4, f4 = li & 15;                  \
            cpa16(sB + (((buf) * 32 + k) * 72 + f4 * 4) * 4,                    \
                  hb + (size_t)((kc) * 32 + k) * CC + f4 * 4);                  \
        }                                                                       \
        cp_commit();                                                            \
    }

    HOP_ISSUE(0, 0);
    for (int kc = 0; kc < 16; ++kc) {
        if (kc + 1 < 16) { HOP_ISSUE(kc + 1, (kc + 1) & 1); cp_wait<1>(); }
        else cp_wait<0>();
        __syncthreads();
        const float* Ab = As + (kc & 1) * 256 * 36;
        const float* Bb = Bs + (kc & 1) * 32 * 72;
#pragma unroll
        for (int ks = 0; ks < 4; ++ks) {
            uint32_t af[4][4], bf[4][2];
#pragma unroll
            for (int mt = 0; mt < 4; ++mt) {
                const float* pA = Ab + (wM * 64 + mt * 16 + grp) * 36 + ks * 8 + q;
                af[mt][0] = __float_as_uint(pA[0]);
                af[mt][1] = __float_as_uint(pA[8 * 36]);
                af[mt][2] = __float_as_uint(pA[4]);
                af[mt][3] = __float_as_uint(pA[8 * 36 + 4]);
            }
#pragma unroll
            for (int nt = 0; nt < 4; ++nt) {
                const float* pB = Bb + (ks * 8 + q) * 72 + wN * 32 + nt * 8 + grp;
                bf[nt][0] = __float_as_uint(pB[0]);
                bf[nt][1] = __float_as_uint(pB[4 * 72]);
            }
#pragma unroll
            for (int mt = 0; mt < 4; ++mt)
#pragma unroll
                for (int nt = 0; nt < 4; ++nt)
                    mma8(acc[mt][nt], af[mt], bf[nt]);
        }
        __syncthreads();
    }

    const float om = 1.f - ALPHA;
#pragma unroll
    for (int mt = 0; mt < 4; ++mt) {
#pragma unroll
        for (int half = 0; half < 2; ++half) {
            int row = n0 + wM * 64 + mt * 16 + grp + half * 8;
            size_t rb = ((size_t)bt * NNODE + row) * CC + wN * 32 + 2 * q;
#pragma unroll
            for (int nt = 0; nt < 4; ++nt) {
                size_t a = rb + nt * 8;
                float d0 = acc[mt][nt][half * 2 + 0];
                float d1 = acc[mt][nt][half * 2 + 1];
                float2 h0 = *reinterpret_cast<const float2*>(&g_h[a]);
                float o0 = tf32r(ALPHA * h0.x + om * d0);
                float o1 = tf32r(ALPHA * h0.y + om * d1);
                *reinterpret_cast<float2*>(&hout[a]) = make_float2(o0, o1);
            }
        }
    }
}

// =============================================================================
// final: out = concat5@Wfin[:,:64]+b+x ; skip = h@Ws+bs. CTA 128x128, K=320
// =============================================================================
__global__ __launch_bounds__(256, 2) void final_mma(const float* __restrict__ x,
                                                    float* __restrict__ out) {
    extern __shared__ float smem[];
    float* As = smem;                 // [2][128][36]
    float* Bs = smem + CONV_AS;       // [2][32][136]
    const int r0 = blockIdx.x * 128;
    const int tid = threadIdx.x;
    const int w = tid >> 5, lane = tid & 31;
    const int grp = lane >> 2, q = lane & 3;
    const int wM = w & 1, wN = w >> 1;
    const uint32_t sA = s2u(As), sB = s2u(Bs);

    float acc[4][4][4];
#pragma unroll
    for (int a = 0; a < 4; ++a)
#pragma unroll
        for (int b = 0; b < 4; ++b)
#pragma unroll
            for (int c = 0; c < 4; ++c) acc[a][b][c] = 0.f;

    const float* const srcs[5] = {g_ht, g_h1f, g_h2f, g_h1r, g_h2r};

#define FIN_ISSUE(kc, buf) {                                                    \
        const float* sp = srcs[(kc) >> 1] + ((kc) & 1) * 32;                    \
        _Pragma("unroll")                                                       \
        for (int i = 0; i < 4; ++i) {                                           \
            int li = tid + i * 256, row = li >> 3, c4 = li & 7;                 \
            cpa16(sA + (((buf) * 128 + row) * 36 + c4 * 4) * 4,                 \
                  sp + (size_t)(r0 + row) * CC + c4 * 4);                       \
        }                                                                       \
        const float* wb = g_Wfin + (kc) * 32 * 128;                             \
        _Pragma("unroll")                                                       \
        for (int i = 0; i < 4; ++i) {                                           \
            int li = tid + i * 256, k = li >> 5, c4 = li & 31;                  \
            cpa16(sB + (((buf) * 32 + k) * 136 + c4 * 4) * 4,                   \
                  wb + k * 128 + c4 * 4);                                       \
        }                                                                       \
        cp_commit();                                                            \
    }

    FIN_ISSUE(0, 0);
    for (int kc = 0; kc < 10; ++kc) {
        if (kc + 1 < 10) { FIN_ISSUE(kc + 1, (kc + 1) & 1); cp_wait<1>(); }
        else cp_wait<0>();
        __syncthreads();
        const float* Ab = As + (kc & 1) * 128 * 36;
        const float* Bb = Bs + (kc & 1) * 32 * 136;
#pragma unroll
        for (int ks = 0; ks < 4; ++ks) {
            uint32_t af[4][4], bf[4][2];
#pragma unroll
            for (int mt = 0; mt < 4; ++mt) {
                const float* pA = Ab + (wM * 64 + mt * 16 + grp) * 36 + ks * 8 + q;
                af[mt][0] = __float_as_uint(pA[0]);
                af[mt][1] = __float_as_uint(pA[8 * 36]);
                af[mt][2] = __float_as_uint(pA[4]);
                af[mt][3] = __float_as_uint(pA[8 * 36 + 4]);
            }
#pragma unroll
            for (int nt = 0; nt < 4; ++nt) {
                const float* pB = Bb + (ks * 8 + q) * 136 + wN * 32 + nt * 8 + grp;
                bf[nt][0] = __float_as_uint(pB[0]);
                bf[nt][1] = __float_as_uint(pB[4 * 136]);
            }
#pragma unroll
            for (int mt = 0; mt < 4; ++mt)
#pragma unroll
                for (int nt = 0; nt < 4; ++nt)
                    mma8(acc[mt][nt], af[mt], bf[nt]);
        }
        __syncthreads();
    }

#pragma unroll
    for (int mt = 0; mt < 4; ++mt) {
#pragma unroll
        for (int half = 0; half < 2; ++half) {
            int row = r0 + wM * 64 + mt * 16 + grp + half * 8;
#pragma unroll
            for (int nt = 0; nt < 4; ++nt) {
                int col = wN * 32 + nt * 8 + 2 * q;
                float d0 = acc[mt][nt][half * 2 + 0] + g_bfin[col];
                float d1 = acc[mt][nt][half * 2 + 1] + g_bfin[col + 1];
                if (wN < 2) {  // out half: + residual x
                    size_t a = (size_t)row * CC + col;
                    float2 xr = *reinterpret_cast<const float2*>(&x[a]);
                    *reinterpret_cast<float2*>(&out[a]) =
                        make_float2(d0 + xr.x, d1 + xr.y);
                } else {       // skip half
                    size_t a = (size_t)HN + (size_t)row * CC + (col - 64);
                    *reinterpret_cast<float2*>(&out[a]) = make_float2(d0, d1);
                }
            }
        }
    }
}

// ---------------- launch ------------------------------------------------------
extern "C" void kernel_launch(void* const* d_in, const int* in_sizes, int n_in,
                              void* d_out, int out_size) {
    P p;
    p.x   = (const float*)d_in[0];
    p.adj = (const float*)d_in[1];
    for (int b = 0; b < 4; ++b) {
        p.wf[b] = (const float*)d_in[2 + b * 4 + 0];
        p.bf[b] = (const float*)d_in[2 + b * 4 + 1];
        p.wg[b] = (const float*)d_in[2 + b * 4 + 2];
        p.bg[b] = (const float*)d_in[2 + b * 4 + 3];
    }
    p.Wgf = (const float*)d_in[18];
    p.bgf = (const float*)d_in[19];
    p.Wgr = (const float*)d_in[20];
    p.bgr = (const float*)d_in[21];
    p.Ws  = (const float*)d_in[22];
    p.bs  = (const float*)d_in[23];
    float* out = (float*)d_out;

    const int convSmem = (CONV_AS + CONV_BS) * 4;   // 71680 B
    const int hopSmem  = (HOP_AS + HOP_BS) * 4;     // 92160 B
    cudaFuncSetAttribute(conv_mma,  cudaFuncAttributeMaxDynamicSharedMemorySize, convSmem);
    cudaFuncSetAttribute(hop_mma,   cudaFuncAttributeMaxDynamicSharedMemorySize, hopSmem);
    cudaFuncSetAttribute(final_mma, cudaFuncAttributeMaxDynamicSharedMemorySize, convSmem);

    prep_adj<<<NNODE, 256>>>(p.adj);
    prep_w<<<385, 256>>>(p);
    prep_xt<<<HN / 4 / 256, 256>>>(p.x);

    dim3 gc(4, BT);
    conv_mma<<<gc, 256, convSmem>>>();

    dim3 gh(2, BT);
    hop_mma<<<gh, 256, hopSmem>>>(0, 0);
    hop_mma<<<gh, 256, hopSmem>>>(0, 1);
    hop_mma<<<gh, 256, hopSmem>>>(1, 0);
    hop_mma<<<gh, 256, hopSmem>>>(1, 1);

    final_mma<<<BTN / 128, 256, convSmem>>>(p.x, out);
}

// round 5
// speedup vs baseline: 7.1822x; 1.4234x over previous
#include <cuda_runtime.h>
#include <cuda_fp16.h>
#include <cstdint>
#include <math.h>

#define NNODE 512
#define CC 64
#define BT 2048
#define BTN 1048576
#define HN 67108864ULL
#define ALPHA 0.05f

// ---------------- device scratch (half operands, allocation-free) -------------
__device__ __half g_xh  [HN];          // x fp16 [bt][n][c]
__device__ __half g_hh  [HN];          // h [bt][n][f]
__device__ __half g_hTh [HN];          // h [bt][f][n]
__device__ __half g_h1fR[HN];          // hop1 fwd [n][f]
__device__ __half g_h1fT[HN];          // hop1 fwd [f][n]
__device__ __half g_h1rR[HN];
__device__ __half g_h1rT[HN];
__device__ __half g_h2f [HN];          // hop2 [n][f]
__device__ __half g_h2r [HN];
__device__ __half g_Afh [NNODE*NNODE]; // row-norm adj fp16
__device__ __half g_Arh [NNODE*NNODE];
__device__ __half g_WpadTh[7*128*64];  // [d][cout(interleaved 2j=f,2j+1=g)][cin]
__device__ float  g_bconv[128];
__device__ __half g_WfinTh[128*320];   // [cout][k]  cout<64 out, >=64 skip
__device__ float  g_bfin[128];

struct P {
    const float* x; const float* adj;
    const float* wf[4]; const float* bf[4];
    const float* wg[4]; const float* bg[4];
    const float* Wgf; const float* bgf;
    const float* Wgr; const float* bgr;
    const float* Ws;  const float* bs;
};

// ---------------- helpers -----------------------------------------------------
__device__ __forceinline__ void mma16(float* d, const uint32_t* a, const uint32_t* b) {
    asm volatile(
        "mma.sync.aligned.m16n8k16.row.col.f32.f16.f16.f32 "
        "{%0,%1,%2,%3}, {%4,%5,%6,%7}, {%8,%9}, {%0,%1,%2,%3};\n"
        : "+f"(d[0]), "+f"(d[1]), "+f"(d[2]), "+f"(d[3])
        : "r"(a[0]), "r"(a[1]), "r"(a[2]), "r"(a[3]), "r"(b[0]), "r"(b[1]));
}
__device__ __forceinline__ void cpa16(uint32_t dst, const void* src) {
    asm volatile("cp.async.cg.shared.global [%0], [%1], 16;" :: "r"(dst), "l"(src));
}
__device__ __forceinline__ void cp_commit() { asm volatile("cp.async.commit_group;"); }
template<int N> __device__ __forceinline__ void cp_wait() {
    asm volatile("cp.async.wait_group %0;" :: "n"(N) : "memory");
}
__device__ __forceinline__ uint32_t s2u(const void* p) {
    return (uint32_t)__cvta_generic_to_shared(p);
}
__device__ __forceinline__ uint32_t packh2(float a, float b) {
    __half2 h = __floats2half2_rn(a, b);
    return *reinterpret_cast<uint32_t*>(&h);
}
__device__ __forceinline__ float2 unph2(uint32_t u) {
    __half2 h = *reinterpret_cast<__half2*>(&u);
    return __half22float2(h);
}

// ---------------- prep: adjacencies (fp16) ------------------------------------
__global__ void prep_adj(const float* __restrict__ adj) {
    int n = blockIdx.x, tid = threadIdx.x;
    __shared__ float red[256];
    float s1 = 0.f, s2 = 0.f;
    for (int m = tid; m < NNODE; m += 256) {
        s1 += adj[n * NNODE + m];
        s2 += adj[m * NNODE + n];
    }
    red[tid] = s1; __syncthreads();
    for (int k = 128; k; k >>= 1) { if (tid < k) red[tid] += red[tid + k]; __syncthreads(); }
    float inv1 = 1.f / fmaxf(red[0] + 1.f, 1e-9f);
    __syncthreads();
    red[tid] = s2; __syncthreads();
    for (int k = 128; k; k >>= 1) { if (tid < k) red[tid] += red[tid + k]; __syncthreads(); }
    float inv2 = 1.f / fmaxf(red[0] + 1.f, 1e-9f);
    for (int m = tid; m < NNODE; m += 256) {
        g_Afh[n * NNODE + m] = __float2half_rn((adj[n * NNODE + m] + (m == n ? 1.f : 0.f)) * inv1);
        g_Arh[n * NNODE + m] = __float2half_rn((adj[m * NNODE + n] + (m == n ? 1.f : 0.f)) * inv2);
    }
}

// ---------------- prep: weights ------------------------------------------------
__global__ void prep_w(P p) {
    int idx = blockIdx.x * blockDim.x + threadIdx.x;
    const int KR[4] = {2, 3, 6, 7};
    if (idx < 57344) {                   // WpadTh[d][c][cin]
        int d = idx / 8192;
        int c = (idx >> 6) & 127;
        int cin = idx & 63;
        int j = c >> 1, gsel = c & 1;
        int i = j >> 4, r = j & 15;
        int k = KR[i], jj = k - 1 - d;
        float v = 0.f;
        if (jj >= 0) {
            const float* w = gsel ? p.wg[i] : p.wf[i];
            v = w[(jj * 64 + cin) * 16 + r];
        }
        g_WpadTh[idx] = __float2half_rn(v);
        return;
    }
    int i2 = idx - 57344;
    if (i2 < 128) {
        int j = i2 >> 1, gsel = i2 & 1;
        int i = j >> 4, r = j & 15;
        g_bconv[i2] = gsel ? p.bg[i][r] : p.bf[i][r];
        return;
    }
    int i3 = idx - 57472;
    if (i3 < 40960) {                    // WfinTh[c][k]
        int c = i3 / 320, k = i3 % 320;
        float v = 0.f;
        if (c < 64) {
            int s = k >> 6, kk = k & 63;
            if      (s == 0) v = p.Wgf[kk * 64 + c] + p.Wgr[kk * 64 + c];
            else if (s == 1) v = p.Wgf[( 64 + kk) * 64 + c];
            else if (s == 2) v = p.Wgf[(128 + kk) * 64 + c];
            else if (s == 3) v = p.Wgr[( 64 + kk) * 64 + c];
            else             v = p.Wgr[(128 + kk) * 64 + c];
        } else {
            if (k < 64) v = p.Ws[k * 64 + (c - 64)];
        }
        g_WfinTh[i3] = __float2half_rn(v);
        return;
    }
    int i4 = idx - 98432;
    if (i4 >= 0 && i4 < 128)
        g_bfin[i4] = (i4 < 64) ? (p.bgf[i4] + p.bgr[i4]) : p.bs[i4 - 64];
}

// ---------------- prep: x -> fp16 ----------------------------------------------
__global__ void prep_xh(const float* __restrict__ x) {
    size_t i = (size_t)(blockIdx.x * blockDim.x + threadIdx.x) * 8;
    float4 v0 = *reinterpret_cast<const float4*>(x + i);
    float4 v1 = *reinterpret_cast<const float4*>(x + i + 4);
    uint4 o;
    o.x = packh2(v0.x, v0.y); o.y = packh2(v0.z, v0.w);
    o.z = packh2(v1.x, v1.y); o.w = packh2(v1.z, v1.w);
    *reinterpret_cast<uint4*>(g_xh + i) = o;
}

// =============================================================================
// conv: CTA 128 n x 128 cout, K = 2*min(t+1,7) chunks of 32
// =============================================================================
__global__ __launch_bounds__(256, 2) void conv_fp16() {
    extern __shared__ __align__(16) __half smemh[];
    __half* As = smemh;                  // 2 x [128][40]
    __half* Bs = smemh + 2 * 5120;       // 2 x [128][40]
    const uint32_t sA = s2u(As), sB = s2u(Bs);
    const int bt = blockIdx.y, t = bt & 255, n0 = blockIdx.x * 128;
    const int tid = threadIdx.x, w = tid >> 5, lane = tid & 31;
    const int grp = lane >> 2, q = lane & 3;
    const int wM = w & 1, wN = w >> 1;
    const int NC = 2 * ((t + 1 < 7) ? (t + 1) : 7);

    float acc[4][4][4];
#pragma unroll
    for (int a = 0; a < 4; ++a)
#pragma unroll
        for (int b = 0; b < 4; ++b)
#pragma unroll
            for (int c = 0; c < 4; ++c) acc[a][b][c] = 0.f;

#define CONV_ISSUE(kc, buf) {                                                   \
        int d_ = (kc) >> 1, c0_ = ((kc) & 1) * 32;                              \
        const __half* xb = g_xh + ((size_t)(bt - d_) * NNODE + n0) * CC + c0_;  \
        const __half* wb = g_WpadTh + d_ * 8192 + c0_;                          \
        _Pragma("unroll")                                                       \
        for (int i = 0; i < 2; ++i) {                                           \
            int li = tid + i * 256, row = li >> 2, seg = li & 3;                \
            cpa16(sA + ((buf) * 5120 + row * 40 + seg * 8) * 2,                 \
                  xb + (size_t)row * CC + seg * 8);                             \
            cpa16(sB + ((buf) * 5120 + row * 40 + seg * 8) * 2,                 \
                  wb + row * 64 + seg * 8);                                     \
        }                                                                       \
        cp_commit();                                                            \
    }

    CONV_ISSUE(0, 0);
    for (int kc = 0; kc < NC; ++kc) {
        if (kc + 1 < NC) { CONV_ISSUE(kc + 1, (kc + 1) & 1); cp_wait<1>(); }
        else cp_wait<0>();
        __syncthreads();
        const __half* Ab = As + (kc & 1) * 5120;
        const __half* Bb = Bs + (kc & 1) * 5120;
#pragma unroll
        for (int ks = 0; ks < 2; ++ks) {
            uint32_t af[4][4], bf[4][2];
#pragma unroll
            for (int mt = 0; mt < 4; ++mt) {
                int row = wM * 64 + mt * 16 + grp;
                af[mt][0] = *(const uint32_t*)&Ab[row * 40 + ks * 16 + 2 * q];
                af[mt][1] = *(const uint32_t*)&Ab[(row + 8) * 40 + ks * 16 + 2 * q];
                af[mt][2] = *(const uint32_t*)&Ab[row * 40 + ks * 16 + 2 * q + 8];
                af[mt][3] = *(const uint32_t*)&Ab[(row + 8) * 40 + ks * 16 + 2 * q + 8];
            }
#pragma unroll
            for (int nt = 0; nt < 4; ++nt) {
                int rb = wN * 32 + nt * 8 + grp;
                bf[nt][0] = *(const uint32_t*)&Bb[rb * 40 + ks * 16 + 2 * q];
                bf[nt][1] = *(const uint32_t*)&Bb[rb * 40 + ks * 16 + 2 * q + 8];
            }
#pragma unroll
            for (int mt = 0; mt < 4; ++mt)
#pragma unroll
                for (int nt = 0; nt < 4; ++nt)
                    mma16(acc[mt][nt], af[mt], bf[nt]);
        }
        __syncthreads();
    }

    // epilogue: gated activation -> stage S[n 128][72], then dual coalesced writes
    __half* S = As;                      // 128*72*2 = 18432 <= 20480
#pragma unroll
    for (int mt = 0; mt < 4; ++mt)
#pragma unroll
        for (int hf = 0; hf < 2; ++hf) {
            int rl = wM * 64 + mt * 16 + grp + hf * 8;
#pragma unroll
            for (int nt = 0; nt < 4; ++nt) {
                int j = wN * 16 + nt * 4 + q;
                float f = acc[mt][nt][hf * 2 + 0] + g_bconv[2 * j];
                float g = acc[mt][nt][hf * 2 + 1] + g_bconv[2 * j + 1];
                float th = 1.f - 2.f / (__expf(2.f * f) + 1.f);
                float sg = 1.f / (1.f + __expf(-g));
                S[rl * 72 + j] = __float2half_rn(th * sg);
            }
        }
    __syncthreads();
#pragma unroll
    for (int i = 0; i < 4; ++i) {        // g_hh [n][f]
        int li = tid + i * 256, row = li >> 3, seg = li & 7;
        *reinterpret_cast<uint4*>(g_hh + ((size_t)bt * NNODE + n0 + row) * CC + seg * 8) =
            *reinterpret_cast<uint4*>(&S[row * 72 + seg * 8]);
    }
#pragma unroll
    for (int i = 0; i < 16; ++i) {       // g_hTh [f][n]
        int li = tid + i * 256, f = li >> 6, np = li & 63;
        uint32_t u = ((uint32_t)__half_as_ushort(S[(2 * np) * 72 + f])) |
                     ((uint32_t)__half_as_ushort(S[(2 * np + 1) * 72 + f]) << 16);
        *reinterpret_cast<uint32_t*>(g_hTh + ((size_t)bt * CC + f) * NNODE + n0 + 2 * np) = u;
    }
}

// =============================================================================
// hop: CTA 256 n x 64 f, K=512. out = alpha*h + (1-alpha)*A@hin
// =============================================================================
__global__ __launch_bounds__(256, 2) void hop_fp16(int dir, int hop) {
    extern __shared__ __align__(16) __half smemh[];
    __half* As = smemh;                  // 2 x [256][40]
    __half* Bs = smemh + 2 * 10240;      // 2 x [64][40]
    const uint32_t sA = s2u(As), sB = s2u(Bs);
    const __half* Aadj = dir ? g_Arh : g_Afh;
    const __half* inT  = hop ? (dir ? g_h1rT : g_h1fT) : g_hTh;
    __half* outR = hop ? (dir ? g_h2r : g_h2f) : (dir ? g_h1rR : g_h1fR);
    __half* outT = dir ? g_h1rT : g_h1fT;

    const int bt = blockIdx.y, n0 = blockIdx.x * 256;
    const int tid = threadIdx.x, w = tid >> 5, lane = tid & 31;
    const int grp = lane >> 2, q = lane & 3;
    const int wM = w & 3, wN = w >> 2;

    float acc[4][4][4];
#pragma unroll
    for (int a = 0; a < 4; ++a)
#pragma unroll
        for (int b = 0; b < 4; ++b)
#pragma unroll
            for (int c = 0; c < 4; ++c) acc[a][b][c] = 0.f;

#define HOP_ISSUE(kc, buf) {                                                    \
        _Pragma("unroll")                                                       \
        for (int i = 0; i < 4; ++i) {                                           \
            int li = tid + i * 256, row = li >> 2, seg = li & 3;                \
            cpa16(sA + ((buf) * 10240 + row * 40 + seg * 8) * 2,                \
                  Aadj + (size_t)(n0 + row) * NNODE + (kc) * 32 + seg * 8);     \
        }                                                                       \
        {                                                                       \
            int row = tid >> 2, seg = tid & 3;                                  \
            cpa16(sB + ((buf) * 2560 + row * 40 + seg * 8) * 2,                 \
                  inT + ((size_t)bt * CC + row) * NNODE + (kc) * 32 + seg * 8); \
        }                                                                       \
        cp_commit();                                                            \
    }

    HOP_ISSUE(0, 0);
    for (int kc = 0; kc < 16; ++kc) {
        if (kc + 1 < 16) { HOP_ISSUE(kc + 1, (kc + 1) & 1); cp_wait<1>(); }
        else cp_wait<0>();
        __syncthreads();
        const __half* Ab = As + (kc & 1) * 10240;
        const __half* Bb = Bs + (kc & 1) * 2560;
#pragma unroll
        for (int ks = 0; ks < 2; ++ks) {
            uint32_t af[4][4], bf[4][2];
#pragma unroll
            for (int mt = 0; mt < 4; ++mt) {
                int row = wM * 64 + mt * 16 + grp;
                af[mt][0] = *(const uint32_t*)&Ab[row * 40 + ks * 16 + 2 * q];
                af[mt][1] = *(const uint32_t*)&Ab[(row + 8) * 40 + ks * 16 + 2 * q];
                af[mt][2] = *(const uint32_t*)&Ab[row * 40 + ks * 16 + 2 * q + 8];
                af[mt][3] = *(const uint32_t*)&Ab[(row + 8) * 40 + ks * 16 + 2 * q + 8];
            }
#pragma unroll
            for (int nt = 0; nt < 4; ++nt) {
                int rb = wN * 32 + nt * 8 + grp;
                bf[nt][0] = *(const uint32_t*)&Bb[rb * 40 + ks * 16 + 2 * q];
                bf[nt][1] = *(const uint32_t*)&Bb[rb * 40 + ks * 16 + 2 * q + 8];
            }
#pragma unroll
            for (int mt = 0; mt < 4; ++mt)
#pragma unroll
                for (int nt = 0; nt < 4; ++nt)
                    mma16(acc[mt][nt], af[mt], bf[nt]);
        }
        __syncthreads();
    }

    // stage raw acc (rounded) into S[n 256][72]
    __half* S = As;                      // 256*72*2 = 36864 <= 40960
#pragma unroll
    for (int mt = 0; mt < 4; ++mt)
#pragma unroll
        for (int hf = 0; hf < 2; ++hf) {
            int rl = wM * 64 + mt * 16 + grp + hf * 8;
#pragma unroll
            for (int nt = 0; nt < 4; ++nt) {
                int col = wN * 32 + nt * 8 + 2 * q;
                *reinterpret_cast<uint32_t*>(&S[rl * 72 + col]) =
                    packh2(acc[mt][nt][hf * 2 + 0], acc[mt][nt][hf * 2 + 1]);
            }
        }
    __syncthreads();

    const float om = 1.f - ALPHA;
    // pass 1: outR [n][f], blended with g_hh (all coalesced 16B)
#pragma unroll
    for (int i = 0; i < 8; ++i) {
        int li = tid + i * 256, row = li >> 3, seg = li & 7;
        size_t ga = ((size_t)bt * NNODE + n0 + row) * CC + seg * 8;
        uint4 sa = *reinterpret_cast<uint4*>(&S[row * 72 + seg * 8]);
        uint4 ha = *reinterpret_cast<const uint4*>(g_hh + ga);
        uint4 o;
        uint32_t* sp = &sa.x; uint32_t* hp = &ha.x; uint32_t* op = &o.x;
#pragma unroll
        for (int k = 0; k < 4; ++k) {
            float2 av = unph2(sp[k]), hv = unph2(hp[k]);
            op[k] = packh2(ALPHA * hv.x + om * av.x, ALPHA * hv.y + om * av.y);
        }
        *reinterpret_cast<uint4*>(outR + ga) = o;
    }
    // pass 2 (hop0 only): outT [f][n], blended with g_hTh
    if (hop == 0) {
#pragma unroll
        for (int i = 0; i < 32; ++i) {
            int li = tid + i * 256, f = li >> 7, np = li & 127;
            size_t ga = ((size_t)bt * CC + f) * NNODE + n0 + 2 * np;
            float a0 = __half2float(S[(2 * np) * 72 + f]);
            float a1 = __half2float(S[(2 * np + 1) * 72 + f]);
            float2 hv = unph2(*reinterpret_cast<const uint32_t*>(g_hTh + ga));
            *reinterpret_cast<uint32_t*>(outT + ga) =
                packh2(ALPHA * hv.x + om * a0, ALPHA * hv.y + om * a1);
        }
    }
}

// =============================================================================
// final: CTA 128 rows x 128 cols (64 out + 64 skip), K=320
// =============================================================================
__global__ __launch_bounds__(256, 2) void final_fp16(const float* __restrict__ x,
                                                     float* __restrict__ out) {
    extern __shared__ __align__(16) __half smemh[];
    __half* As = smemh;                  // 2 x [128][40]
    __half* Bs = smemh + 2 * 5120;
    const uint32_t sA = s2u(As), sB = s2u(Bs);
    const int r0 = blockIdx.x * 128;
    const int tid = threadIdx.x, w = tid >> 5, lane = tid & 31;
    const int grp = lane >> 2, q = lane & 3;
    const int wM = w & 1, wN = w >> 1;

    float acc[4][4][4];
#pragma unroll
    for (int a = 0; a < 4; ++a)
#pragma unroll
        for (int b = 0; b < 4; ++b)
#pragma unroll
            for (int c = 0; c < 4; ++c) acc[a][b][c] = 0.f;

    const __half* const srcs[5] = {g_hh, g_h1fR, g_h2f, g_h1rR, g_h2r};

#define FIN_ISSUE(kc, buf) {                                                    \
        const __half* sp = srcs[(kc) >> 1] + ((kc) & 1) * 32;                   \
        _Pragma("unroll")                                                       \
        for (int i = 0; i < 2; ++i) {                                           \
            int li = tid + i * 256, row = li >> 2, seg = li & 3;                \
            cpa16(sA + ((buf) * 5120 + row * 40 + seg * 8) * 2,                 \
                  sp + (size_t)(r0 + row) * CC + seg * 8);                      \
            cpa16(sB + ((buf) * 5120 + row * 40 + seg * 8) * 2,                 \
                  g_WfinTh + row * 320 + (kc) * 32 + seg * 8);                  \
        }                                                                       \
        cp_commit();                                                            \
    }

    FIN_ISSUE(0, 0);
    for (int kc = 0; kc < 10; ++kc) {
        if (kc + 1 < 10) { FIN_ISSUE(kc + 1, (kc + 1) & 1); cp_wait<1>(); }
        else cp_wait<0>();
        __syncthreads();
        const __half* Ab = As + (kc & 1) * 5120;
        const __half* Bb = Bs + (kc & 1) * 5120;
#pragma unroll
        for (int ks = 0; ks < 2; ++ks) {
            uint32_t af[4][4], bf[4][2];
#pragma unroll
            for (int mt = 0; mt < 4; ++mt) {
                int row = wM * 64 + mt * 16 + grp;
                af[mt][0] = *(const uint32_t*)&Ab[row * 40 + ks * 16 + 2 * q];
                af[mt][1] = *(const uint32_t*)&Ab[(row + 8) * 40 + ks * 16 + 2 * q];
                af[mt][2] = *(const uint32_t*)&Ab[row * 40 + ks * 16 + 2 * q + 8];
                af[mt][3] = *(const uint32_t*)&Ab[(row + 8) * 40 + ks * 16 + 2 * q + 8];
            }
#pragma unroll
            for (int nt = 0; nt < 4; ++nt) {
                int rb = wN * 32 + nt * 8 + grp;
                bf[nt][0] = *(const uint32_t*)&Bb[rb * 40 + ks * 16 + 2 * q];
                bf[nt][1] = *(const uint32_t*)&Bb[rb * 40 + ks * 16 + 2 * q + 8];
            }
#pragma unroll
            for (int mt = 0; mt < 4; ++mt)
#pragma unroll
                for (int nt = 0; nt < 4; ++nt)
                    mma16(acc[mt][nt], af[mt], bf[nt]);
        }
        __syncthreads();
    }

#pragma unroll
    for (int mt = 0; mt < 4; ++mt)
#pragma unroll
        for (int hf = 0; hf < 2; ++hf) {
            int row = r0 + wM * 64 + mt * 16 + grp + hf * 8;
#pragma unroll
            for (int nt = 0; nt < 4; ++nt) {
                int col = wN * 32 + nt * 8 + 2 * q;
                float d0 = acc[mt][nt][hf * 2 + 0] + g_bfin[col];
                float d1 = acc[mt][nt][hf * 2 + 1] + g_bfin[col + 1];
                if (wN < 2) {   // out half: + residual x
                    size_t a = (size_t)row * CC + col;
                    float2 xr = *reinterpret_cast<const float2*>(&x[a]);
                    *reinterpret_cast<float2*>(&out[a]) = make_float2(d0 + xr.x, d1 + xr.y);
                } else {        // skip half
                    size_t a = HN + (size_t)row * CC + (col - 64);
                    *reinterpret_cast<float2*>(&out[a]) = make_float2(d0, d1);
                }
            }
        }
}

// ---------------- launch ------------------------------------------------------
extern "C" void kernel_launch(void* const* d_in, const int* in_sizes, int n_in,
                              void* d_out, int out_size) {
    P p;
    p.x   = (const float*)d_in[0];
    p.adj = (const float*)d_in[1];
    for (int b = 0; b < 4; ++b) {
        p.wf[b] = (const float*)d_in[2 + b * 4 + 0];
        p.bf[b] = (const float*)d_in[2 + b * 4 + 1];
        p.wg[b] = (const float*)d_in[2 + b * 4 + 2];
        p.bg[b] = (const float*)d_in[2 + b * 4 + 3];
    }
    p.Wgf = (const float*)d_in[18];
    p.bgf = (const float*)d_in[19];
    p.Wgr = (const float*)d_in[20];
    p.bgr = (const float*)d_in[21];
    p.Ws  = (const float*)d_in[22];
    p.bs  = (const float*)d_in[23];
    float* out = (float*)d_out;

    const int smemCF = 4 * 5120 * 2;                 // 40960 B (conv/final)
    const int smemH  = (2 * 10240 + 2 * 2560) * 2;   // 51200 B (hop)
    static int inited = 0;
    if (!inited) {
        cudaFuncSetAttribute(hop_fp16, cudaFuncAttributeMaxDynamicSharedMemorySize, smemH);
        inited = 1;
    }

    prep_adj<<<NNODE, 256>>>(p.adj);
    prep_w<<<385, 256>>>(p);
    prep_xh<<<HN / 8 / 256, 256>>>(p.x);

    dim3 gc(4, BT);
    conv_fp16<<<gc, 256, smemCF>>>();

    dim3 gh(2, BT);
    hop_fp16<<<gh, 256, smemH>>>(0, 0);
    hop_fp16<<<gh, 256, smemH>>>(1, 0);
    hop_fp16<<<gh, 256, smemH>>>(0, 1);
    hop_fp16<<<gh, 256, smemH>>>(1, 1);

    final_fp16<<<BTN / 128, 256, smemCF>>>(p.x, out);
}